// round 1
// baseline (speedup 1.0000x reference)
#include <cuda_runtime.h>

// ---------------- problem constants ----------------
#define BATCH  8
#define HGRID  64
#define WGRID  64
#define WFREQ  33           // WGRID/2 + 1
#define NBLK   8
#define BSZ    128
#define CH     1024         // NBLK*BSZ
#define NPOS   (BATCH*HGRID*WFREQ)   // 16896
#define PLANE  (NPOS*CH)             // 17301504
#define LAMB   0.01f

// ---------------- static scratch (no allocations allowed) ----------------
__device__ float g_Ar[PLANE];
__device__ float g_Ai[PLANE];
__device__ float g_Br[PLANE];
__device__ float g_Bi[PLANE];
__device__ float2 g_tw[64];   // (cos, sin)(2*pi*j/64)

// ---------------- twiddle init (deterministic, every call) ----------------
__global__ void k_init_tw() {
    int j = threadIdx.x;
    if (j < 64) {
        float s, c;
        sincospif((float)j * (1.0f / 32.0f), &s, &c);   // angle = 2*pi*j/64
        g_tw[j] = make_float2(c, s);
    }
}

// ---------------- stage 1: rfft along W (raw, unnormalized) ----------------
// thread = (b,h,c). x layout: ((b*64+h)*64 + w)*1024 + c
__global__ __launch_bounds__(256) void k_rfft_w(const float* __restrict__ x) {
    int g  = blockIdx.x * 256 + threadIdx.x;   // 524288 threads
    int c  = g & (CH - 1);
    int bh = g >> 10;                          // b*64 + h, 0..511
    float v[64];
    const float* xp = x + (size_t)bh * WGRID * CH + c;
    #pragma unroll
    for (int w = 0; w < 64; w++) v[w] = xp[w * CH];
    int orow = bh * WFREQ;
    for (int wf = 0; wf <= 32; wf++) {
        float ar = 0.f, ai = 0.f;
        int idx = 0;
        #pragma unroll
        for (int w = 0; w < 64; w++) {
            float2 t = g_tw[idx];
            idx = (idx + wf) & 63;
            ar = fmaf(v[w],  t.x, ar);   // e^{-i th}: Re
            ai = fmaf(-v[w], t.y, ai);   //            Im
        }
        g_Ar[(size_t)(orow + wf) * CH + c] = ar;
        g_Ai[(size_t)(orow + wf) * CH + c] = ai;
    }
}

// ---------------- stage 2/5: complex DFT along H ----------------
// INV=0: forward e^{-i th}, scale 1/64 (ortho forward), A -> B
// INV=1: inverse e^{+i th}, scale 1,                    B -> A
template <int INV>
__global__ __launch_bounds__(128) void k_fft_h() {
    int g  = blockIdx.x * 128 + threadIdx.x;   // 270336 threads
    int c  = g & (CH - 1);
    int bw = g >> 10;                          // 0..263
    int wf = bw % WFREQ;
    int b  = bw / WFREQ;
    const float* inr = INV ? g_Br : g_Ar;
    const float* ini = INV ? g_Bi : g_Ai;
    float* outr      = INV ? g_Ar : g_Br;
    float* outi      = INV ? g_Ai : g_Bi;
    const size_t hstride = (size_t)WFREQ * CH;
    size_t base = ((size_t)(b * HGRID) * WFREQ + wf) * CH + c;
    float ar[64], ai[64];
    #pragma unroll
    for (int h = 0; h < 64; h++) {
        ar[h] = inr[base + h * hstride];
        ai[h] = ini[base + h * hstride];
    }
    const float sc = INV ? 1.0f : (1.0f / 64.0f);
    for (int hf = 0; hf < 64; hf++) {
        float xr = 0.f, xi = 0.f;
        int idx = 0;
        #pragma unroll
        for (int h = 0; h < 64; h++) {
            float2 t = g_tw[idx];
            idx = (idx + hf) & 63;
            if (INV) {   // (ar+i ai)(c+is)
                xr = fmaf(ar[h], t.x, fmaf(-ai[h], t.y, xr));
                xi = fmaf(ai[h], t.x, fmaf( ar[h], t.y, xi));
            } else {     // (ar+i ai)(c-is)
                xr = fmaf(ar[h], t.x, fmaf( ai[h], t.y, xr));
                xi = fmaf(ai[h], t.x, fmaf(-ar[h], t.y, xi));
            }
        }
        outr[base + hf * hstride] = xr * sc;
        outi[base + hf * hstride] = xi * sc;
    }
}

// ---------------- stage 3/4: block-diagonal complex MLP layer ----------------
// LAYER 1: (g_Br,g_Bi) -> relu -> (g_Ar,g_Ai)
// LAYER 2: (g_Ar,g_Ai) -> softshrink -> (g_Br,g_Bi)
// Per block k: Or = Xr@W0 - Xi@W1 + br ; Oi = Xi@W0 + Xr@W1 + bi
// Tile: 128 rows x 128 cols (full block), K-chunk 16, 256 threads, 8x8x2 acc/thread.
template <int LAYER>
__global__ __launch_bounds__(256) void k_mlp(const float* __restrict__ Wt,
                                             const float* __restrict__ bias) {
    const float* Inr = (LAYER == 1) ? g_Br : g_Ar;
    const float* Ini = (LAYER == 1) ? g_Bi : g_Ai;
    float* Outr      = (LAYER == 1) ? g_Ar : g_Br;
    float* Outi      = (LAYER == 1) ? g_Ai : g_Bi;

    int kb = blockIdx.y;
    int p0 = blockIdx.x * 128;
    const float* W0 = Wt + (size_t)kb * BSZ * BSZ;            // w[0][kb][i][o]
    const float* W1 = Wt + (size_t)(NBLK + kb) * BSZ * BSZ;   // w[1][kb][i][o]

    __shared__ __align__(16) float sAr[128 * 16];
    __shared__ __align__(16) float sAi[128 * 16];
    __shared__ __align__(16) float sW0[16 * 128];
    __shared__ __align__(16) float sW1[16 * 128];

    int tid  = threadIdx.x;
    int col0 = (tid & 15) * 8;
    int row0 = (tid >> 4) * 8;

    float accR[8][8], accI[8][8];
    #pragma unroll
    for (int r = 0; r < 8; r++)
        #pragma unroll
        for (int q = 0; q < 8; q++) { accR[r][q] = 0.f; accI[r][q] = 0.f; }

    for (int k0 = 0; k0 < 128; k0 += 16) {
        // load A tile: 128 rows x 16 k (r & i)
        {
            int lk = tid & 15, lr = tid >> 4;   // 16 rows per pass, x8
            #pragma unroll
            for (int it = 0; it < 8; it++) {
                int row = lr + it * 16;
                size_t gi = (size_t)(p0 + row) * CH + kb * BSZ + k0 + lk;
                sAr[row * 16 + lk] = Inr[gi];
                sAi[row * 16 + lk] = Ini[gi];
            }
            // load W tiles: 16 k x 128 cols
            int wc = tid & 127, wr = tid >> 7;  // 2 rows per pass, x8
            #pragma unroll
            for (int it = 0; it < 8; it++) {
                int kr = wr + it * 2;
                sW0[kr * 128 + wc] = W0[(size_t)(k0 + kr) * 128 + wc];
                sW1[kr * 128 + wc] = W1[(size_t)(k0 + kr) * 128 + wc];
            }
        }
        __syncthreads();
        #pragma unroll
        for (int kk = 0; kk < 16; kk++) {
            float arf[8], aif[8], w0f[8], w1f[8];
            #pragma unroll
            for (int r = 0; r < 8; r++) {
                arf[r] = sAr[(row0 + r) * 16 + kk];
                aif[r] = sAi[(row0 + r) * 16 + kk];
            }
            float4 u0 = *(const float4*)&sW0[kk * 128 + col0];
            float4 u1 = *(const float4*)&sW0[kk * 128 + col0 + 4];
            float4 v0 = *(const float4*)&sW1[kk * 128 + col0];
            float4 v1 = *(const float4*)&sW1[kk * 128 + col0 + 4];
            w0f[0]=u0.x; w0f[1]=u0.y; w0f[2]=u0.z; w0f[3]=u0.w;
            w0f[4]=u1.x; w0f[5]=u1.y; w0f[6]=u1.z; w0f[7]=u1.w;
            w1f[0]=v0.x; w1f[1]=v0.y; w1f[2]=v0.z; w1f[3]=v0.w;
            w1f[4]=v1.x; w1f[5]=v1.y; w1f[6]=v1.z; w1f[7]=v1.w;
            #pragma unroll
            for (int r = 0; r < 8; r++)
                #pragma unroll
                for (int q = 0; q < 8; q++) {
                    accR[r][q] = fmaf(arf[r], w0f[q], fmaf(-aif[r], w1f[q], accR[r][q]));
                    accI[r][q] = fmaf(aif[r], w0f[q], fmaf( arf[r], w1f[q], accI[r][q]));
                }
        }
        __syncthreads();
    }

    // epilogue
    const float* bR = bias + (size_t)kb * BSZ;
    const float* bI = bias + (size_t)(NBLK + kb) * BSZ;
    float brv[8], biv[8];
    #pragma unroll
    for (int q = 0; q < 8; q++) { brv[q] = bR[col0 + q]; biv[q] = bI[col0 + q]; }
    #pragma unroll
    for (int r = 0; r < 8; r++) {
        size_t o = (size_t)(p0 + row0 + r) * CH + kb * BSZ + col0;
        #pragma unroll
        for (int q = 0; q < 8; q++) {
            float vr = accR[r][q] + brv[q];
            float vi = accI[r][q] + biv[q];
            if (LAYER == 1) {
                vr = fmaxf(vr, 0.f);
                vi = fmaxf(vi, 0.f);
            } else {
                vr = (vr > LAMB) ? vr - LAMB : ((vr < -LAMB) ? vr + LAMB : 0.f);
                vi = (vi > LAMB) ? vi - LAMB : ((vi < -LAMB) ? vi + LAMB : 0.f);
            }
            Outr[o + q] = vr;
            Outi[o + q] = vi;
        }
    }
}

// ---------------- stage 6: inverse rDFT along W + residual ----------------
// Hermitian reconstruction (ignores Im of DC & Nyquist like C2R), scale 1/64.
__global__ __launch_bounds__(256) void k_irfft_w(const float* __restrict__ x,
                                                 float* __restrict__ out) {
    int g  = blockIdx.x * 256 + threadIdx.x;   // 524288 threads
    int c  = g & (CH - 1);
    int bh = g >> 10;
    float zr[33], zi[33];
    size_t base = (size_t)bh * WFREQ * CH + c;
    #pragma unroll
    for (int wf = 0; wf < 33; wf++) {
        zr[wf] = g_Ar[base + wf * CH];
        zi[wf] = g_Ai[base + wf * CH];
    }
    size_t obase = (size_t)bh * WGRID * CH + c;
    for (int w = 0; w < 64; w++) {
        float s0 = zr[0] + ((w & 1) ? -zr[32] : zr[32]);
        float acc = 0.f;
        int idx = w & 63;   // wf=1 term: angle index = w
        #pragma unroll
        for (int wf = 1; wf <= 31; wf++) {
            float2 t = g_tw[idx];
            idx = (idx + w) & 63;
            acc = fmaf(zr[wf], t.x, fmaf(-zi[wf], t.y, acc));  // Re(Z * e^{+i th})
        }
        float val = (s0 + 2.f * acc) * (1.0f / 64.0f);
        out[obase + w * CH] = val + x[obase + w * CH];
    }
}

// ---------------- launch ----------------
extern "C" void kernel_launch(void* const* d_in, const int* in_sizes, int n_in,
                              void* d_out, int out_size) {
    const float* x  = (const float*)d_in[0];
    const float* w1 = (const float*)d_in[1];
    const float* b1 = (const float*)d_in[2];
    const float* w2 = (const float*)d_in[3];
    const float* b2 = (const float*)d_in[4];
    float* out = (float*)d_out;
    (void)in_sizes; (void)n_in; (void)out_size;

    k_init_tw<<<1, 64>>>();
    k_rfft_w<<<(BATCH*HGRID*CH)/256, 256>>>(x);          // 2048 blocks
    k_fft_h<0><<<(BATCH*WFREQ*CH)/128, 128>>>();         // 2112 blocks
    k_mlp<1><<<dim3(NPOS/128, NBLK), 256>>>(w1, b1);     // 132 x 8
    k_mlp<2><<<dim3(NPOS/128, NBLK), 256>>>(w2, b2);     // 132 x 8
    k_fft_h<1><<<(BATCH*WFREQ*CH)/128, 128>>>();         // 2112 blocks
    k_irfft_w<<<(BATCH*HGRID*CH)/256, 256>>>(x, out);    // 2048 blocks
}